// round 8
// baseline (speedup 1.0000x reference)
#include <cuda_runtime.h>
#include <cuda_bf16.h>

// GaussianKernel via bf16 tensor-core GEMM, round 7:
//   out[b,l,o] = exp(-gamma*(|x|^2 + |w|^2 - 2 x.w)) + bias[o]
// GEMM [M=131072, N=64, K=288]. Changes vs 68us version:
//  - A stored in natural [k][l] bf16 layout (no software transpose; short
//    LDG->cvt->STS.64 chain, higher MLP)
//  - 16B-chunk XOR swizzle (^ k&7) -> ldmatrix.x4.trans A-fragment loads,
//    conflict-free: 18 LDSM/thread replaces 72 LDS.32
//  - A pitch 256B -> smem 111.4KB, still 2 CTAs/SM

#define K_DIM   288
#define O_DIM   64
#define L_DIM   16384
#define TPB     256
#define MT      128
#define KSTEPS  18
#define A_PITCH_B 256                      // bytes per A row (128 bf16)

#define WF_UINT4 (KSTEPS * 4 * 32)         // 2304 uint4 = 36864 B

__device__ uint4 g_wf[WF_UINT4];           // packed B fragments
__device__ float g_w2[O_DIM];

// smem layout (bytes)
#define A_BYTES   (K_DIM * A_PITCH_B)      // 73728
#define SMEM_WF   (A_BYTES)
#define SMEM_W2   (SMEM_WF + WF_UINT4 * 16)
#define SMEM_X2   (SMEM_W2 + O_DIM * 4)
#define SMEM_TOT  (SMEM_X2 + MT * 4)       // 111360 B

// ---------------------------------------------------------------------------
// Init: pack w[k][n] into m16n8k16 B fragments + |w|^2 (runs once per replay).
__global__ void gauss_init_kernel(const float* __restrict__ w)
{
    const int e = blockIdx.x * 256 + threadIdx.x;
    if (e < WF_UINT4) {
        const int lane = e & 31, nbp = (e >> 5) & 3, s = e >> 7;
        const int t = lane & 3, g = lane >> 2;
        const int k0 = s * 16 + t * 2;
        const int n0 = (2 * nbp) * 8 + g;
        const int n1 = n0 + 8;
        uint4 r;
        __nv_bfloat162 p;
        p = __float22bfloat162_rn(make_float2(w[(size_t)k0 * O_DIM + n0],
                                              w[(size_t)(k0 + 1) * O_DIM + n0]));
        r.x = *(unsigned*)&p;
        p = __float22bfloat162_rn(make_float2(w[(size_t)(k0 + 8) * O_DIM + n0],
                                              w[(size_t)(k0 + 9) * O_DIM + n0]));
        r.y = *(unsigned*)&p;
        p = __float22bfloat162_rn(make_float2(w[(size_t)k0 * O_DIM + n1],
                                              w[(size_t)(k0 + 1) * O_DIM + n1]));
        r.z = *(unsigned*)&p;
        p = __float22bfloat162_rn(make_float2(w[(size_t)(k0 + 8) * O_DIM + n1],
                                              w[(size_t)(k0 + 9) * O_DIM + n1]));
        r.w = *(unsigned*)&p;
        g_wf[e] = r;
    }
    if (blockIdx.x == 0 && threadIdx.x < O_DIM) {
        float s = 0.f;
        #pragma unroll 8
        for (int k = 0; k < K_DIM; k++) {
            const float v = w[(size_t)k * O_DIM + threadIdx.x];
            s = fmaf(v, v, s);
        }
        g_w2[threadIdx.x] = s;
    }
}

// ---------------------------------------------------------------------------
__global__ void __launch_bounds__(TPB, 2)
gauss_mma_kernel(const float* __restrict__ x,
                 const float* __restrict__ bias,
                 const float* __restrict__ gptr,
                 float* __restrict__ out)
{
    extern __shared__ char smem[];
    char*     Ab  = smem;                            // A: [288][256B], swizzled
    uint4*    wfs = (uint4*)(smem + SMEM_WF);        // [18*4][32]
    float*    w2s = (float*)(smem + SMEM_W2);
    float*    x2s = (float*)(smem + SMEM_X2);

    const int tid  = threadIdx.x;
    const int lane = tid & 31;
    const int wp   = tid >> 5;                       // 0..7

    const int m0 = blockIdx.x * MT;                  // 1024 CTAs
    const int b  = m0 >> 14;
    const int lb = m0 & (L_DIM - 1);
    const float* xb = x + (size_t)b * K_DIM * L_DIM + lb;

    // ---- Copy packed w fragments + w2 to smem ----
    #pragma unroll
    for (int i = 0; i < WF_UINT4 / TPB; i++)         // 9
        wfs[tid + TPB * i] = g_wf[tid + TPB * i];
    if (tid < O_DIM) w2s[tid] = g_w2[tid];

    // ---- Load A: x[k][l] fp32 -> bf16 [k][l] smem (swizzled), |x|^2 in regs.
    // thread: lsub = lane&3, ksl = lane>>2; l = (wp*4+lsub)*4 + {0..3};
    // k = p*8 + ksl, p = 0..35. LDG.128 coalesced (4 lanes = 64B per k-row).
    {
        const int lsub = lane & 3;
        const int ksl  = lane >> 2;                  // 0..7 == k&7
        const int l0t  = (wp * 4 + lsub) * 4;
        const float* xp = xb + l0t;
        // swizzle: byte = k*256 + ((l0t*2) ^ (ksl*16))
        char* ap = Ab + ((l0t * 2) ^ (ksl * 16)) + (size_t)ksl * A_PITCH_B;
        float s0 = 0.f, s1 = 0.f, s2 = 0.f, s3 = 0.f;
        #pragma unroll 6
        for (int p = 0; p < 36; p++) {
            const float4 v = __ldg((const float4*)(xp + (size_t)(p * 8 + ksl) * L_DIM));
            s0 = fmaf(v.x, v.x, s0);
            s1 = fmaf(v.y, v.y, s1);
            s2 = fmaf(v.z, v.z, s2);
            s3 = fmaf(v.w, v.w, s3);
            __nv_bfloat162 lo = __float22bfloat162_rn(make_float2(v.x, v.y));
            __nv_bfloat162 hi = __float22bfloat162_rn(make_float2(v.z, v.w));
            *(uint2*)(ap + (size_t)p * 8 * A_PITCH_B) =
                make_uint2(*(unsigned*)&lo, *(unsigned*)&hi);
        }
        // butterfly over ksl (lane bits 2..4)
        #pragma unroll
        for (int m = 4; m <= 16; m <<= 1) {
            s0 += __shfl_xor_sync(0xffffffffu, s0, m);
            s1 += __shfl_xor_sync(0xffffffffu, s1, m);
            s2 += __shfl_xor_sync(0xffffffffu, s2, m);
            s3 += __shfl_xor_sync(0xffffffffu, s3, m);
        }
        if (ksl == 0) {
            x2s[l0t]     = s0;
            x2s[l0t + 1] = s1;
            x2s[l0t + 2] = s2;
            x2s[l0t + 3] = s3;
        }
    }
    __syncthreads();

    // ---- Main GEMM: warp wp covers l rows wp*16..+15; ldmatrix.x4.trans A ----
    const int g = lane >> 2;
    const int t = lane & 3;
    const int row = wp * 16 + g;

    // ldmatrix source address (per s, step 16 rows = 4096B):
    // k-row-in-step = (lane&7) | ((lane>>4)<<3); chunk = (2*wp + ((lane>>3)&1)) ^ (lane&7)
    unsigned aAddr;
    {
        const int kr = (lane & 7) | ((lane >> 4) << 3);
        const int cb = 2 * wp + ((lane >> 3) & 1);
        const char* p = Ab + (size_t)kr * A_PITCH_B + ((cb ^ (lane & 7)) * 16);
        aAddr = (unsigned)__cvta_generic_to_shared(p);
    }

    float c[8][4];
    #pragma unroll
    for (int nb = 0; nb < 8; nb++)
        #pragma unroll
        for (int q = 0; q < 4; q++) c[nb][q] = 0.f;

    #pragma unroll
    for (int s = 0; s < KSTEPS; s++) {
        unsigned a0, a1, a2, a3;
        asm volatile(
            "ldmatrix.sync.aligned.m8n8.x4.trans.shared.b16 {%0,%1,%2,%3}, [%4];\n"
            : "=r"(a0), "=r"(a1), "=r"(a2), "=r"(a3)
            : "r"(aAddr + s * 16 * A_PITCH_B));
        #pragma unroll
        for (int nbp = 0; nbp < 4; nbp++) {
            const uint4 bb = wfs[(s * 4 + nbp) * 32 + lane];
            asm volatile(
                "mma.sync.aligned.m16n8k16.row.col.f32.bf16.bf16.f32 "
                "{%0,%1,%2,%3}, {%4,%5,%6,%7}, {%8,%9}, {%0,%1,%2,%3};\n"
                : "+f"(c[2*nbp][0]), "+f"(c[2*nbp][1]), "+f"(c[2*nbp][2]), "+f"(c[2*nbp][3])
                : "r"(a0), "r"(a1), "r"(a2), "r"(a3), "r"(bb.x), "r"(bb.y));
            asm volatile(
                "mma.sync.aligned.m16n8k16.row.col.f32.bf16.bf16.f32 "
                "{%0,%1,%2,%3}, {%4,%5,%6,%7}, {%8,%9}, {%0,%1,%2,%3};\n"
                : "+f"(c[2*nbp+1][0]), "+f"(c[2*nbp+1][1]), "+f"(c[2*nbp+1][2]), "+f"(c[2*nbp+1][3])
                : "r"(a0), "r"(a1), "r"(a2), "r"(a3), "r"(bb.z), "r"(bb.w));
        }
    }

    // ---- Epilogue ----
    const float ng  = -(*gptr);
    const float xa  = x2s[row];
    const float xb2 = x2s[row + 8];
    float* orow0 = out + (size_t)(m0 + row)     * O_DIM;
    float* orow1 = out + (size_t)(m0 + row + 8) * O_DIM;
    #pragma unroll
    for (int nb = 0; nb < 8; nb++) {
        const int o  = nb * 8 + t * 2;
        const float w20 = w2s[o], w21 = w2s[o + 1];
        const float bi0 = __ldg(bias + o), bi1 = __ldg(bias + o + 1);
        float2 r0, r1;
        r0.x = __expf(ng * (xa  + w20 - 2.f * c[nb][0])) + bi0;
        r0.y = __expf(ng * (xa  + w21 - 2.f * c[nb][1])) + bi1;
        r1.x = __expf(ng * (xb2 + w20 - 2.f * c[nb][2])) + bi0;
        r1.y = __expf(ng * (xb2 + w21 - 2.f * c[nb][3])) + bi1;
        *(float2*)(orow0 + o) = r0;
        *(float2*)(orow1 + o) = r1;
    }
}

extern "C" void kernel_launch(void* const* d_in, const int* in_sizes, int n_in,
                              void* d_out, int out_size)
{
    (void)in_sizes; (void)n_in; (void)out_size;
    const float* x     = (const float*)d_in[0];   // [8, 288, 16384]
    const float* w     = (const float*)d_in[1];   // [64,32,3,3] == flat [288][64]
    const float* bias  = (const float*)d_in[2];   // [64]
    const float* gamma = (const float*)d_in[3];   // scalar
    float* out = (float*)d_out;                   // [8, 16384, 64]

    cudaFuncSetAttribute(gauss_mma_kernel,
                         cudaFuncAttributeMaxDynamicSharedMemorySize, SMEM_TOT);

    gauss_init_kernel<<<(WF_UINT4 + 255) / 256, 256>>>(w);
    const int grid = (8 * L_DIM) / MT;            // 1024 CTAs
    gauss_mma_kernel<<<grid, TPB, SMEM_TOT>>>(x, bias, gamma, out);
}

// round 9
// speedup vs baseline: 1.0675x; 1.0675x over previous
#include <cuda_runtime.h>
#include <cuda_bf16.h>

// GaussianKernel via bf16 tensor-core GEMM, round 8:
//   out[b,l,o] = exp(-gamma*(|x|^2 + |w|^2 - 2 x.w)) + bias[o]
// GEMM [M=131072, N=64, K=288]. Change vs 68us version: K split into two
// 144-wide halves through one 36.9KB A buffer -> smem 74.5KB -> 3 CTAs/SM
// (24 warps/SM, occupancy ceiling 23.7% -> ~35%). Load unroll 9 for MLP.

#define K_DIM   288
#define K_HALF  144
#define O_DIM   64
#define L_DIM   16384
#define TPB     256
#define MT      128
#define KSTEPS  18                         // total mma k-steps (9 per half)
#define A_PITCH_B 256                      // bytes per A row (128 bf16)

#define WF_UINT4 (KSTEPS * 4 * 32)         // 2304 uint4 = 36864 B

__device__ uint4 g_wf[WF_UINT4];           // packed B fragments
__device__ float g_w2[O_DIM];

// smem layout (bytes)
#define A_BYTES   (K_HALF * A_PITCH_B)     // 36864
#define SMEM_WF   (A_BYTES)
#define SMEM_W2   (SMEM_WF + WF_UINT4 * 16)
#define SMEM_X2   (SMEM_W2 + O_DIM * 4)
#define SMEM_TOT  (SMEM_X2 + MT * 4)       // 74496 B

// ---------------------------------------------------------------------------
__global__ void gauss_init_kernel(const float* __restrict__ w)
{
    const int e = blockIdx.x * 256 + threadIdx.x;
    if (e < WF_UINT4) {
        const int lane = e & 31, nbp = (e >> 5) & 3, s = e >> 7;
        const int t = lane & 3, g = lane >> 2;
        const int k0 = s * 16 + t * 2;
        const int n0 = (2 * nbp) * 8 + g;
        const int n1 = n0 + 8;
        uint4 r;
        __nv_bfloat162 p;
        p = __float22bfloat162_rn(make_float2(w[(size_t)k0 * O_DIM + n0],
                                              w[(size_t)(k0 + 1) * O_DIM + n0]));
        r.x = *(unsigned*)&p;
        p = __float22bfloat162_rn(make_float2(w[(size_t)(k0 + 8) * O_DIM + n0],
                                              w[(size_t)(k0 + 9) * O_DIM + n0]));
        r.y = *(unsigned*)&p;
        p = __float22bfloat162_rn(make_float2(w[(size_t)k0 * O_DIM + n1],
                                              w[(size_t)(k0 + 1) * O_DIM + n1]));
        r.z = *(unsigned*)&p;
        p = __float22bfloat162_rn(make_float2(w[(size_t)(k0 + 8) * O_DIM + n1],
                                              w[(size_t)(k0 + 9) * O_DIM + n1]));
        r.w = *(unsigned*)&p;
        g_wf[e] = r;
    }
    if (blockIdx.x == 0 && threadIdx.x < O_DIM) {
        float s = 0.f;
        #pragma unroll 8
        for (int k = 0; k < K_DIM; k++) {
            const float v = w[(size_t)k * O_DIM + threadIdx.x];
            s = fmaf(v, v, s);
        }
        g_w2[threadIdx.x] = s;
    }
}

// ---------------------------------------------------------------------------
__global__ void __launch_bounds__(TPB, 3)
gauss_mma_kernel(const float* __restrict__ x,
                 const float* __restrict__ bias,
                 const float* __restrict__ gptr,
                 float* __restrict__ out)
{
    extern __shared__ char smem[];
    char*     Ab  = smem;                            // A: [144][256B], swizzled
    uint4*    wfs = (uint4*)(smem + SMEM_WF);        // [18*4][32]
    float*    w2s = (float*)(smem + SMEM_W2);
    float*    x2s = (float*)(smem + SMEM_X2);

    const int tid  = threadIdx.x;
    const int lane = tid & 31;
    const int wp   = tid >> 5;                       // 0..7

    const int m0 = blockIdx.x * MT;                  // 1024 CTAs
    const int b  = m0 >> 14;
    const int lb = m0 & (L_DIM - 1);
    const float* xb = x + (size_t)b * K_DIM * L_DIM + lb;

    // ---- Copy packed w fragments + w2 to smem ----
    #pragma unroll
    for (int i = 0; i < WF_UINT4 / TPB; i++)         // 9
        wfs[tid + TPB * i] = g_wf[tid + TPB * i];
    if (tid < O_DIM) w2s[tid] = g_w2[tid];

    // Load mapping: lsub = lane&3, ksl = lane>>2; l = (wp*4+lsub)*4 + {0..3};
    // per half: k = h*144 + p*8 + ksl, p = 0..17.
    const int lsub = lane & 3;
    const int ksl  = lane >> 2;                      // k&7
    const int l0t  = (wp * 4 + lsub) * 4;
    const float* xp = xb + l0t;
    char* ap = Ab + ((l0t * 2) ^ (ksl * 16)) + (size_t)ksl * A_PITCH_B;
    float s0 = 0.f, s1 = 0.f, s2 = 0.f, s3 = 0.f;

    // ldmatrix source address (kr = row within 16-row step)
    unsigned aAddr;
    {
        const int kr = (lane & 7) | ((lane >> 4) << 3);
        const int cb = 2 * wp + ((lane >> 3) & 1);
        const char* p = Ab + (size_t)kr * A_PITCH_B + ((cb ^ (lane & 7)) * 16);
        aAddr = (unsigned)__cvta_generic_to_shared(p);
    }

    const int g = lane >> 2;
    const int t = lane & 3;
    const int row = wp * 16 + g;

    float c[8][4];
    #pragma unroll
    for (int nb = 0; nb < 8; nb++)
        #pragma unroll
        for (int q = 0; q < 4; q++) c[nb][q] = 0.f;

    #pragma unroll
    for (int h = 0; h < 2; h++) {
        // ---- Load half h: 18 rows per thread, unroll 9 for MLP ----
        const float* xph = xp + (size_t)(h * K_HALF + ksl) * L_DIM;
        #pragma unroll 9
        for (int p = 0; p < 18; p++) {
            const float4 v = __ldg((const float4*)(xph + (size_t)(p * 8) * L_DIM));
            s0 = fmaf(v.x, v.x, s0);
            s1 = fmaf(v.y, v.y, s1);
            s2 = fmaf(v.z, v.z, s2);
            s3 = fmaf(v.w, v.w, s3);
            __nv_bfloat162 lo = __float22bfloat162_rn(make_float2(v.x, v.y));
            __nv_bfloat162 hi = __float22bfloat162_rn(make_float2(v.z, v.w));
            *(uint2*)(ap + (size_t)p * 8 * A_PITCH_B) =
                make_uint2(*(unsigned*)&lo, *(unsigned*)&hi);
        }
        if (h == 1) {
            // finalize |x|^2: butterfly over ksl (lane bits 2..4)
            #pragma unroll
            for (int m = 4; m <= 16; m <<= 1) {
                s0 += __shfl_xor_sync(0xffffffffu, s0, m);
                s1 += __shfl_xor_sync(0xffffffffu, s1, m);
                s2 += __shfl_xor_sync(0xffffffffu, s2, m);
                s3 += __shfl_xor_sync(0xffffffffu, s3, m);
            }
            if (ksl == 0) {
                x2s[l0t]     = s0;
                x2s[l0t + 1] = s1;
                x2s[l0t + 2] = s2;
                x2s[l0t + 3] = s3;
            }
        }
        __syncthreads();

        // ---- MMA half h: 9 k-steps ----
        #pragma unroll
        for (int s = 0; s < 9; s++) {
            unsigned a0, a1, a2, a3;
            asm volatile(
                "ldmatrix.sync.aligned.m8n8.x4.trans.shared.b16 {%0,%1,%2,%3}, [%4];\n"
                : "=r"(a0), "=r"(a1), "=r"(a2), "=r"(a3)
                : "r"(aAddr + s * 16 * A_PITCH_B));
            const int sg = h * 9 + s;
            #pragma unroll
            for (int nbp = 0; nbp < 4; nbp++) {
                const uint4 bb = wfs[(sg * 4 + nbp) * 32 + lane];
                asm volatile(
                    "mma.sync.aligned.m16n8k16.row.col.f32.bf16.bf16.f32 "
                    "{%0,%1,%2,%3}, {%4,%5,%6,%7}, {%8,%9}, {%0,%1,%2,%3};\n"
                    : "+f"(c[2*nbp][0]), "+f"(c[2*nbp][1]), "+f"(c[2*nbp][2]), "+f"(c[2*nbp][3])
                    : "r"(a0), "r"(a1), "r"(a2), "r"(a3), "r"(bb.x), "r"(bb.y));
                asm volatile(
                    "mma.sync.aligned.m16n8k16.row.col.f32.bf16.bf16.f32 "
                    "{%0,%1,%2,%3}, {%4,%5,%6,%7}, {%8,%9}, {%0,%1,%2,%3};\n"
                    : "+f"(c[2*nbp+1][0]), "+f"(c[2*nbp+1][1]), "+f"(c[2*nbp+1][2]), "+f"(c[2*nbp+1][3])
                    : "r"(a0), "r"(a1), "r"(a2), "r"(a3), "r"(bb.z), "r"(bb.w));
            }
        }
        if (h == 0) __syncthreads();   // A buffer reused by half 1
    }

    // ---- Epilogue ----
    const float ng  = -(*gptr);
    const float xa  = x2s[row];
    const float xb2 = x2s[row + 8];
    float* orow0 = out + (size_t)(m0 + row)     * O_DIM;
    float* orow1 = out + (size_t)(m0 + row + 8) * O_DIM;
    #pragma unroll
    for (int nb = 0; nb < 8; nb++) {
        const int o  = nb * 8 + t * 2;
        const float w20 = w2s[o], w21 = w2s[o + 1];
        const float bi0 = __ldg(bias + o), bi1 = __ldg(bias + o + 1);
        float2 r0, r1;
        r0.x = __expf(ng * (xa  + w20 - 2.f * c[nb][0])) + bi0;
        r0.y = __expf(ng * (xa  + w21 - 2.f * c[nb][1])) + bi1;
        r1.x = __expf(ng * (xb2 + w20 - 2.f * c[nb][2])) + bi0;
        r1.y = __expf(ng * (xb2 + w21 - 2.f * c[nb][3])) + bi1;
        *(float2*)(orow0 + o) = r0;
        *(float2*)(orow1 + o) = r1;
    }
}

extern "C" void kernel_launch(void* const* d_in, const int* in_sizes, int n_in,
                              void* d_out, int out_size)
{
    (void)in_sizes; (void)n_in; (void)out_size;
    const float* x     = (const float*)d_in[0];   // [8, 288, 16384]
    const float* w     = (const float*)d_in[1];   // [64,32,3,3] == flat [288][64]
    const float* bias  = (const float*)d_in[2];   // [64]
    const float* gamma = (const float*)d_in[3];   // scalar
    float* out = (float*)d_out;                   // [8, 16384, 64]

    cudaFuncSetAttribute(gauss_mma_kernel,
                         cudaFuncAttributeMaxDynamicSharedMemorySize, SMEM_TOT);

    gauss_init_kernel<<<(WF_UINT4 + 255) / 256, 256>>>(w);
    const int grid = (8 * L_DIM) / MT;            // 1024 CTAs
    gauss_mma_kernel<<<grid, TPB, SMEM_TOT>>>(x, bias, gamma, out);
}

// round 11
// speedup vs baseline: 1.1541x; 1.0811x over previous
#include <cuda_runtime.h>
#include <cuda_bf16.h>

// GaussianKernel via bf16 tensor-core GEMM, round 9:
//   out[b,l,o] = exp(-gamma*(|x|^2 + |w|^2 - 2 x.w)) + bias[o]
// GEMM [M=131072, N=64, K=288]. Change vs 64us version: software pipeline.
// K split into 6 chunks of 48 rows through one 12.3KB A buffer; chunk c+1's
// LDGs are issued before chunk c's mma and consumed at the next STS, so DRAM
// stays busy during compute. smem ~46KB, 3 CTAs/SM, 85-reg cap.

#define K_DIM   288
#define KCHUNK  48
#define NCHUNK  6
#define O_DIM   64
#define L_DIM   16384
#define TPB     256
#define MT      128
#define KSTEPS  18                         // total mma k-steps (3 per chunk)
#define A_PITCH_B 256                      // bytes per A row (128 bf16)

#define WF_UINT4 (KSTEPS * 4 * 32)         // 2304 uint4 = 36864 B

__device__ uint4 g_wf[WF_UINT4];           // packed B fragments
__device__ float g_w2[O_DIM];

// smem layout (bytes)
#define A_BYTES   (KCHUNK * A_PITCH_B)     // 12288
#define SMEM_WF   (A_BYTES)
#define SMEM_W2   (SMEM_WF + WF_UINT4 * 16)
#define SMEM_X2   (SMEM_W2 + O_DIM * 4)
#define SMEM_TOT  (SMEM_X2 + MT * 4)       // 49920 B

// ---------------------------------------------------------------------------
__global__ void gauss_init_kernel(const float* __restrict__ w)
{
    const int e = blockIdx.x * 256 + threadIdx.x;
    if (e < WF_UINT4) {
        const int lane = e & 31, nbp = (e >> 5) & 3, s = e >> 7;
        const int t = lane & 3, g = lane >> 2;
        const int k0 = s * 16 + t * 2;
        const int n0 = (2 * nbp) * 8 + g;
        const int n1 = n0 + 8;
        uint4 r;
        __nv_bfloat162 p;
        p = __float22bfloat162_rn(make_float2(w[(size_t)k0 * O_DIM + n0],
                                              w[(size_t)(k0 + 1) * O_DIM + n0]));
        r.x = *(unsigned*)&p;
        p = __float22bfloat162_rn(make_float2(w[(size_t)(k0 + 8) * O_DIM + n0],
                                              w[(size_t)(k0 + 9) * O_DIM + n0]));
        r.y = *(unsigned*)&p;
        p = __float22bfloat162_rn(make_float2(w[(size_t)k0 * O_DIM + n1],
                                              w[(size_t)(k0 + 1) * O_DIM + n1]));
        r.z = *(unsigned*)&p;
        p = __float22bfloat162_rn(make_float2(w[(size_t)(k0 + 8) * O_DIM + n1],
                                              w[(size_t)(k0 + 9) * O_DIM + n1]));
        r.w = *(unsigned*)&p;
        g_wf[e] = r;
    }
    if (blockIdx.x == 0 && threadIdx.x < O_DIM) {
        float s = 0.f;
        #pragma unroll 8
        for (int k = 0; k < K_DIM; k++) {
            const float v = w[(size_t)k * O_DIM + threadIdx.x];
            s = fmaf(v, v, s);
        }
        g_w2[threadIdx.x] = s;
    }
}

// ---------------------------------------------------------------------------
__global__ void __launch_bounds__(TPB, 3)
gauss_mma_kernel(const float* __restrict__ x,
                 const float* __restrict__ bias,
                 const float* __restrict__ gptr,
                 float* __restrict__ out)
{
    extern __shared__ char smem[];
    char*     Ab  = smem;                            // A: [48][256B], swizzled
    uint4*    wfs = (uint4*)(smem + SMEM_WF);        // [18*4][32]
    float*    w2s = (float*)(smem + SMEM_W2);
    float*    x2s = (float*)(smem + SMEM_X2);

    const int tid  = threadIdx.x;
    const int lane = tid & 31;
    const int wp   = tid >> 5;                       // 0..7

    const int m0 = blockIdx.x * MT;                  // 1024 CTAs
    const int b  = m0 >> 14;
    const int lb = m0 & (L_DIM - 1);
    const float* xb = x + (size_t)b * K_DIM * L_DIM + lb;

    // ---- Copy packed w fragments + w2 to smem ----
    #pragma unroll
    for (int i = 0; i < WF_UINT4 / TPB; i++)         // 9
        wfs[tid + TPB * i] = g_wf[tid + TPB * i];
    if (tid < O_DIM) w2s[tid] = g_w2[tid];

    // Load mapping: lsub = lane&3, ksl = lane>>2; l = (wp*4+lsub)*4 + {0..3};
    // chunk c covers k = c*48 + p*8 + ksl, p = 0..5.
    const int lsub = lane & 3;
    const int ksl  = lane >> 2;                      // k&7
    const int l0t  = (wp * 4 + lsub) * 4;
    const float* xp = xb + l0t + (size_t)ksl * L_DIM;
    char* ap = Ab + ((l0t * 2) ^ (ksl * 16)) + (size_t)ksl * A_PITCH_B;

    // ldmatrix source address (kr = row within 16-row step)
    unsigned aAddr;
    {
        const int kr = (lane & 7) | ((lane >> 4) << 3);
        const int cb = 2 * wp + ((lane >> 3) & 1);
        const char* p = Ab + (size_t)kr * A_PITCH_B + ((cb ^ (lane & 7)) * 16);
        aAddr = (unsigned)__cvta_generic_to_shared(p);
    }

    const int g = lane >> 2;
    const int t = lane & 3;
    const int row = wp * 16 + g;

    float c[8][4];
    #pragma unroll
    for (int nb = 0; nb < 8; nb++)
        #pragma unroll
        for (int q = 0; q < 4; q++) c[nb][q] = 0.f;

    float s0 = 0.f, s1 = 0.f, s2 = 0.f, s3 = 0.f;    // |x|^2 partials
    float4 v[NCHUNK == 0 ? 1 : 6];                   // staging: chunk's 6 LDG.128

    // ---- Prologue: load chunk 0 into registers ----
    #pragma unroll
    for (int p = 0; p < 6; p++)
        v[p] = __ldg((const float4*)(xp + (size_t)(p * 8) * L_DIM));

    // ---- Pipelined main loop ----
    #pragma unroll
    for (int cidx = 0; cidx < NCHUNK; cidx++) {
        __syncthreads();                             // A buffer writable

        // STS chunk cidx from staging regs + x^2 accumulation
        #pragma unroll
        for (int p = 0; p < 6; p++) {
            const float4 vv = v[p];
            s0 = fmaf(vv.x, vv.x, s0);
            s1 = fmaf(vv.y, vv.y, s1);
            s2 = fmaf(vv.z, vv.z, s2);
            s3 = fmaf(vv.w, vv.w, s3);
            __nv_bfloat162 lo = __float22bfloat162_rn(make_float2(vv.x, vv.y));
            __nv_bfloat162 hi = __float22bfloat162_rn(make_float2(vv.z, vv.w));
            *(uint2*)(ap + (size_t)p * 8 * A_PITCH_B) =
                make_uint2(*(unsigned*)&lo, *(unsigned*)&hi);
        }
        __syncthreads();                             // A buffer readable

        // Issue next chunk's LDGs: in flight during the mma below
        if (cidx + 1 < NCHUNK) {
            const float* xn = xp + (size_t)((cidx + 1) * KCHUNK) * L_DIM;
            #pragma unroll
            for (int p = 0; p < 6; p++)
                v[p] = __ldg((const float4*)(xn + (size_t)(p * 8) * L_DIM));
        }

        // mma chunk cidx: 3 k-steps
        #pragma unroll
        for (int s = 0; s < 3; s++) {
            unsigned a0, a1, a2, a3;
            asm volatile(
                "ldmatrix.sync.aligned.m8n8.x4.trans.shared.b16 {%0,%1,%2,%3}, [%4];\n"
                : "=r"(a0), "=r"(a1), "=r"(a2), "=r"(a3)
                : "r"(aAddr + s * 16 * A_PITCH_B));
            const int sg = cidx * 3 + s;
            #pragma unroll
            for (int nbp = 0; nbp < 4; nbp++) {
                const uint4 bb = wfs[(sg * 4 + nbp) * 32 + lane];
                asm volatile(
                    "mma.sync.aligned.m16n8k16.row.col.f32.bf16.bf16.f32 "
                    "{%0,%1,%2,%3}, {%4,%5,%6,%7}, {%8,%9}, {%0,%1,%2,%3};\n"
                    : "+f"(c[2*nbp][0]), "+f"(c[2*nbp][1]), "+f"(c[2*nbp][2]), "+f"(c[2*nbp][3])
                    : "r"(a0), "r"(a1), "r"(a2), "r"(a3), "r"(bb.x), "r"(bb.y));
                asm volatile(
                    "mma.sync.aligned.m16n8k16.row.col.f32.bf16.bf16.f32 "
                    "{%0,%1,%2,%3}, {%4,%5,%6,%7}, {%8,%9}, {%0,%1,%2,%3};\n"
                    : "+f"(c[2*nbp+1][0]), "+f"(c[2*nbp+1][1]), "+f"(c[2*nbp+1][2]), "+f"(c[2*nbp+1][3])
                    : "r"(a0), "r"(a1), "r"(a2), "r"(a3), "r"(bb.z), "r"(bb.w));
            }
        }
    }

    // ---- Finalize |x|^2: butterfly over ksl (lane bits 2..4) ----
    #pragma unroll
    for (int m = 4; m <= 16; m <<= 1) {
        s0 += __shfl_xor_sync(0xffffffffu, s0, m);
        s1 += __shfl_xor_sync(0xffffffffu, s1, m);
        s2 += __shfl_xor_sync(0xffffffffu, s2, m);
        s3 += __shfl_xor_sync(0xffffffffu, s3, m);
    }
    if (ksl == 0) {
        x2s[l0t]     = s0;
        x2s[l0t + 1] = s1;
        x2s[l0t + 2] = s2;
        x2s[l0t + 3] = s3;
    }
    __syncthreads();

    // ---- Epilogue ----
    const float ng  = -(*gptr);
    const float xa  = x2s[row];
    const float xb2 = x2s[row + 8];
    float* orow0 = out + (size_t)(m0 + row)     * O_DIM;
    float* orow1 = out + (size_t)(m0 + row + 8) * O_DIM;
    #pragma unroll
    for (int nb = 0; nb < 8; nb++) {
        const int o  = nb * 8 + t * 2;
        const float w20 = w2s[o], w21 = w2s[o + 1];
        const float bi0 = __ldg(bias + o), bi1 = __ldg(bias + o + 1);
        float2 r0, r1;
        r0.x = __expf(ng * (xa  + w20 - 2.f * c[nb][0])) + bi0;
        r0.y = __expf(ng * (xa  + w21 - 2.f * c[nb][1])) + bi1;
        r1.x = __expf(ng * (xb2 + w20 - 2.f * c[nb][2])) + bi0;
        r1.y = __expf(ng * (xb2 + w21 - 2.f * c[nb][3])) + bi1;
        *(float2*)(orow0 + o) = r0;
        *(float2*)(orow1 + o) = r1;
    }
}

extern "C" void kernel_launch(void* const* d_in, const int* in_sizes, int n_in,
                              void* d_out, int out_size)
{
    (void)in_sizes; (void)n_in; (void)out_size;
    const float* x     = (const float*)d_in[0];   // [8, 288, 16384]
    const float* w     = (const float*)d_in[1];   // [64,32,3,3] == flat [288][64]
    const float* bias  = (const float*)d_in[2];   // [64]
    const float* gamma = (const float*)d_in[3];   // scalar
    float* out = (float*)d_out;                   // [8, 16384, 64]

    cudaFuncSetAttribute(gauss_mma_kernel,
                         cudaFuncAttributeMaxDynamicSharedMemorySize, SMEM_TOT);

    gauss_init_kernel<<<(WF_UINT4 + 255) / 256, 256>>>(w);
    const int grid = (8 * L_DIM) / MT;            // 1024 CTAs
    gauss_mma_kernel<<<grid, TPB, SMEM_TOT>>>(x, bias, gamma, out);
}